// round 17
// baseline (speedup 1.0000x reference)
#include <cuda_runtime.h>

// ---------------------------------------------------------------------------
// MNIST TWN CNN forward, batch 4096, fp32.
// R17: fc1 re-tiled 32x64 (grid 1024 CTAs, 128 thr, 2x8 per-thread tile,
//      lb(128,8)) — fixes grid-limited occupancy (R11 profile: 3.5 CTA/SM).
// Launches: absmax, quantA, quantB, conv1, conv2(#4... wait, #5), bnpool2, fc1, fc2.
// (Profiler captures launch #4 = conv1; conv2 config unchanged from R15/16.)
// ---------------------------------------------------------------------------

#define NIMG 4096
typedef unsigned long long u64;

__device__ __forceinline__ u64 pack2(float lo, float hi) {
    u64 r; asm("mov.b64 %0,{%1,%2};" : "=l"(r) : "f"(lo), "f"(hi)); return r;
}
__device__ __forceinline__ u64 rep2(float v) { return pack2(v, v); }
__device__ __forceinline__ void unpack2(u64 p, float& lo, float& hi) {
    asm("mov.b64 {%0,%1},%2;" : "=f"(lo), "=f"(hi) : "l"(p));
}
__device__ __forceinline__ void ffma2(u64& d, u64 a, u64 b) {
    asm("fma.rn.f32x2 %0,%1,%2,%0;" : "+l"(d) : "l"(a), "l"(b));
}
__device__ __forceinline__ u64 add2(u64 a, u64 b) {
    u64 r; asm("add.rn.f32x2 %0,%1,%2;" : "=l"(r) : "l"(a), "l"(b)); return r;
}
__device__ __forceinline__ float ternary(float w, float t) {
    return (w > t ? 1.0f : 0.0f) - (w < -t ? 1.0f : 0.0f);
}
__device__ __forceinline__ float bnsel(float A, float B, float mx, float mn) {
    return fmaxf(A > 0.f ? fmaf(A, mx, B) : fmaf(A, mn, B), 0.f);
}

// ---- device scratch (static only) -----------------------------------------
static __device__ u64   g_w1p[400];              // [cp][25] packed conv1 weights
static __device__ u64   g_w2p[32 * 800];         // [ci][pc][25] packed conv2 weights
static __device__ float g_wf1q[512 * 1024];
static __device__ float g_wf2q[10 * 512];
static __device__ float g_pmax[96][4];

static __device__ double g_sum1[32],  g_sqs1[32];
static __device__ double g_sum2[64],  g_sqs2[64];
static __device__ double g_sum3[512], g_sqs3[512];

static __device__ float g_m1max[NIMG * 32 * 144];
static __device__ float g_m1min[NIMG * 32 * 144];
static __device__ float g_m2max[NIMG * 1024];
static __device__ float g_m2min[NIMG * 1024];
static __device__ float g_h2[NIMG * 1024];
static __device__ float g_y3[NIMG * 512];

// ---------------------------------------------------------------------------
// Launch 1: abs-max partials (grid MUST be 96). Block 0 zeros stat accums.
// ---------------------------------------------------------------------------
__global__ __launch_bounds__(256) void k_absmax(const float* __restrict__ w1, const float* __restrict__ w2,
                                                const float* __restrict__ wf1, const float* __restrict__ wf2) {
    __shared__ float sm[8][4];
    int tid = threadIdx.x;
    if (blockIdx.x == 0) {
        if (tid < 32) { g_sum1[tid] = 0.0; g_sqs1[tid] = 0.0; }
        if (tid < 64) { g_sum2[tid] = 0.0; g_sqs2[tid] = 0.0; }
        g_sum3[tid] = 0.0;       g_sqs3[tid] = 0.0;
        g_sum3[tid + 256] = 0.0; g_sqs3[tid + 256] = 0.0;
    }
    int gid = blockIdx.x * 256 + tid;
    int stride = 96 * 256;
    float m0 = 0.f, m1 = 0.f, m2 = 0.f, m3 = 0.f;
    for (int i = gid; i < 800;    i += stride) m0 = fmaxf(m0, fabsf(w1[i]));
    for (int i = gid; i < 51200;  i += stride) m1 = fmaxf(m1, fabsf(w2[i]));
    for (int i = gid; i < 524288; i += stride) m2 = fmaxf(m2, fabsf(wf1[i]));
    for (int i = gid; i < 5120;   i += stride) m3 = fmaxf(m3, fabsf(wf2[i]));
    #pragma unroll
    for (int off = 16; off; off >>= 1) {
        m0 = fmaxf(m0, __shfl_xor_sync(0xffffffffu, m0, off));
        m1 = fmaxf(m1, __shfl_xor_sync(0xffffffffu, m1, off));
        m2 = fmaxf(m2, __shfl_xor_sync(0xffffffffu, m2, off));
        m3 = fmaxf(m3, __shfl_xor_sync(0xffffffffu, m3, off));
    }
    int w = tid >> 5;
    if ((tid & 31) == 0) { sm[w][0] = m0; sm[w][1] = m1; sm[w][2] = m2; sm[w][3] = m3; }
    __syncthreads();
    if (tid == 0) {
        float r0 = 0.f, r1 = 0.f, r2 = 0.f, r3 = 0.f;
        #pragma unroll
        for (int i = 0; i < 8; i++) {
            r0 = fmaxf(r0, sm[i][0]); r1 = fmaxf(r1, sm[i][1]);
            r2 = fmaxf(r2, sm[i][2]); r3 = fmaxf(r3, sm[i][3]);
        }
        g_pmax[blockIdx.x][0] = r0; g_pmax[blockIdx.x][1] = r1;
        g_pmax[blockIdx.x][2] = r2; g_pmax[blockIdx.x][3] = r3;
    }
}

__device__ __forceinline__ void block_thr(float* sthr) {
    if (threadIdx.x < 128) {
        int w = threadIdx.x >> 5, lane = threadIdx.x & 31;
        float m = 0.f;
        for (int i = lane; i < 96; i += 32) m = fmaxf(m, g_pmax[i][w]);
        #pragma unroll
        for (int off = 16; off; off >>= 1) m = fmaxf(m, __shfl_xor_sync(0xffffffffu, m, off));
        if (lane == 0) sthr[w] = 0.05f * m;
    }
    __syncthreads();
}

// ---------------------------------------------------------------------------
// Launch 2: quantize conv weights (w1, w2).
// ---------------------------------------------------------------------------
__global__ __launch_bounds__(256) void k_quantA(const float* __restrict__ w1, const float* __restrict__ w2) {
    __shared__ float sthr[4];
    block_thr(sthr);
    float t0 = sthr[0], t1 = sthr[1];
    int gid = blockIdx.x * 256 + threadIdx.x;
    int stride = gridDim.x * 256;
    for (int i = gid; i < 400; i += stride) {
        int cp = i / 25, k = i - cp * 25;
        ((float2*)g_w1p)[i] = make_float2(ternary(w1[(2 * cp) * 25 + k], t0),
                                          ternary(w1[(2 * cp + 1) * 25 + k], t0));
    }
    for (int i = gid; i < 25600; i += stride) {
        int ci = i / 800, r = i - ci * 800;
        int pc = r / 25, k = r - pc * 25;
        ((float2*)g_w2p)[i] = make_float2(ternary(w2[(2 * pc) * 800 + ci * 25 + k], t1),
                                          ternary(w2[(2 * pc + 1) * 800 + ci * 25 + k], t1));
    }
}

// ---------------------------------------------------------------------------
// Launch 3: quantize fc weights (wf1, wf2).
// ---------------------------------------------------------------------------
__global__ __launch_bounds__(256) void k_quantB(const float* __restrict__ wf1, const float* __restrict__ wf2) {
    __shared__ float sthr[4];
    block_thr(sthr);
    float t2 = sthr[2], t3 = sthr[3];
    int gid = blockIdx.x * 256 + threadIdx.x;
    int stride = gridDim.x * 256;
    for (int i = gid; i < 524288; i += stride) g_wf1q[i] = ternary(wf1[i], t2);
    for (int i = gid; i < 5120;   i += stride) g_wf2q[i] = ternary(wf2[i], t3);
}

// ---------------------------------------------------------------------------
// Launch 4: conv1 + stats + pooled max/min. (R16 proven config.)
// ---------------------------------------------------------------------------
__global__ __launch_bounds__(192, 4) void k_conv1(const float* __restrict__ x) {
    __shared__ float sxf[784];
    __shared__ u64 sw1[400];
    __shared__ float somax[32 * 146];
    __shared__ float somin[32 * 146];
    __shared__ float ssum[32], ssq[32];
    int tid = threadIdx.x, n = blockIdx.x;

    if (tid < 32) { ssum[tid] = 0.f; ssq[tid] = 0.f; }
    for (int i = tid; i < 400; i += 192) sw1[i] = g_w1p[i];
    for (int i = tid; i < 784; i += 192) sxf[i] = x[n * 784 + i];
    __syncthreads();

    int cp = tid & 15;
    int q  = tid >> 4;
    const u64* wbase = sw1 + cp * 25;
    u64 sp = 0ull, qp = 0ull;
    int sobase = (2 * cp) * 146 + q * 12;

    #pragma unroll 1
    for (int ob = 0; ob < 24; ob += 4) {
        u64 a0[4] = {0ull, 0ull, 0ull, 0ull};
        u64 a1[4] = {0ull, 0ull, 0ull, 0ull};
        u64 pw0, pw1, pw2, pw3, pw4;
        pw0 = pw1 = pw2 = pw3 = pw4 = 0ull;
        #pragma unroll
        for (int rr = 0; rr < 6; rr++) {
            const float* xr = sxf + (2 * q + rr) * 28 + ob;
            float4 f0 = *(const float4*)xr;
            float4 f1 = *(const float4*)(xr + 4);
            u64 X[8] = { rep2(f0.x), rep2(f0.y), rep2(f0.z), rep2(f0.w),
                         rep2(f1.x), rep2(f1.y), rep2(f1.z), rep2(f1.w) };
            if (rr >= 1) {
                #pragma unroll
                for (int o = 0; o < 4; o++) {
                    ffma2(a1[o], X[o],     pw0);
                    ffma2(a1[o], X[o + 1], pw1);
                    ffma2(a1[o], X[o + 2], pw2);
                    ffma2(a1[o], X[o + 3], pw3);
                    ffma2(a1[o], X[o + 4], pw4);
                }
            }
            if (rr < 5) {
                const u64* wr = wbase + rr * 5;
                u64 c0 = wr[0], c1 = wr[1], c2 = wr[2], c3 = wr[3], c4 = wr[4];
                #pragma unroll
                for (int o = 0; o < 4; o++) {
                    ffma2(a0[o], X[o],     c0);
                    ffma2(a0[o], X[o + 1], c1);
                    ffma2(a0[o], X[o + 2], c2);
                    ffma2(a0[o], X[o + 3], c3);
                    ffma2(a0[o], X[o + 4], c4);
                }
                pw0 = c0; pw1 = c1; pw2 = c2; pw3 = c3; pw4 = c4;
            }
        }
        float r0c0[4], r0c1[4], r1c0[4], r1c1[4];
        #pragma unroll
        for (int o = 0; o < 4; o++) {
            sp = add2(sp, a0[o]); ffma2(qp, a0[o], a0[o]);
            sp = add2(sp, a1[o]); ffma2(qp, a1[o], a1[o]);
            unpack2(a0[o], r0c0[o], r0c1[o]);
            unpack2(a1[o], r1c0[o], r1c1[o]);
        }
        float mx0[2], mn0[2], mx1[2], mn1[2];
        #pragma unroll
        for (int j = 0; j < 2; j++) {
            float A0 = r0c0[2 * j], B0 = r0c0[2 * j + 1], C0 = r1c0[2 * j], D0 = r1c0[2 * j + 1];
            mx0[j] = fmaxf(fmaxf(A0, B0), fmaxf(C0, D0));
            mn0[j] = fminf(fminf(A0, B0), fminf(C0, D0));
            float A1 = r0c1[2 * j], B1 = r0c1[2 * j + 1], C1 = r1c1[2 * j], D1 = r1c1[2 * j + 1];
            mx1[j] = fmaxf(fmaxf(A1, B1), fmaxf(C1, D1));
            mn1[j] = fminf(fminf(A1, B1), fminf(C1, D1));
        }
        int so = sobase + (ob >> 1);
        *(float2*)(somax + so)       = make_float2(mx0[0], mx0[1]);
        *(float2*)(somin + so)       = make_float2(mn0[0], mn0[1]);
        *(float2*)(somax + so + 146) = make_float2(mx1[0], mx1[1]);
        *(float2*)(somin + so + 146) = make_float2(mn1[0], mn1[1]);
    }
    float s0, s1, q0, q1;
    unpack2(sp, s0, s1);
    unpack2(qp, q0, q1);
    atomicAdd(&ssum[2 * cp],     s0);
    atomicAdd(&ssum[2 * cp + 1], s1);
    atomicAdd(&ssq[2 * cp],      q0);
    atomicAdd(&ssq[2 * cp + 1],  q1);
    __syncthreads();

    float* gmx = g_m1max + n * 4608;
    float* gmn = g_m1min + n * 4608;
    for (int i = tid; i < 4608; i += 192) {
        int c = i / 144, p = i - c * 144;
        gmx[i] = somax[c * 146 + p];
        gmn[i] = somin[c * 146 + p];
    }
    if (tid < 32) {
        atomicAdd(&g_sum1[tid], (double)ssum[tid]);
        atomicAdd(&g_sqs1[tid], (double)ssq[tid]);
    }
}

// ---------------------------------------------------------------------------
// Launch 5: conv2 with fin1 in-block. (R15 proven config, lb(256,4).)
// ---------------------------------------------------------------------------
__global__ __launch_bounds__(256, 4) void k_conv2(const float* __restrict__ g1, const float* __restrict__ be1) {
    __shared__ float sin_[2][4608];
    __shared__ u64 swt[2][800];
    __shared__ float sA1[32], sB1[32];
    int tid = threadIdx.x;
    int n0 = blockIdx.x * 2;

    if (tid < 32) {
        const double invM = 1.0 / (4096.0 * 576.0);
        double mean = g_sum1[tid] * invM;
        double var  = g_sqs1[tid] * invM - mean * mean;
        float A = g1[tid] * rsqrtf((float)var + 1e-5f);
        sA1[tid] = A;
        sB1[tid] = be1[tid] - (float)mean * A;
    }
    __syncthreads();

    {
        const float4* mx4 = (const float4*)(g_m1max + n0 * 4608);
        const float4* mn4 = (const float4*)(g_m1min + n0 * 4608);
        float4* s4 = (float4*)sin_;
        for (int i = tid; i < 2304; i += 256) {
            int c = (i % 1152) / 36;
            float A = sA1[c], B = sB1[c];
            float4 mx = mx4[i], mn = mn4[i];
            float4 v;
            v.x = bnsel(A, B, mx.x, mn.x);
            v.y = bnsel(A, B, mx.y, mn.y);
            v.z = bnsel(A, B, mx.z, mn.z);
            v.w = bnsel(A, B, mx.w, mn.w);
            s4[i] = v;
        }
    }
    for (int j = tid; j < 800; j += 256) swt[0][j] = g_w2p[j];
    __syncthreads();

    int img = tid >> 7;
    int t   = tid & 127;
    int pc  = t >> 2;
    int q   = t & 3;
    const float* ib = sin_[img] + q * 24;

    u64 acc[2][8];
    #pragma unroll
    for (int oy = 0; oy < 2; oy++)
        #pragma unroll
        for (int px = 0; px < 8; px++) acc[oy][px] = 0ull;

    for (int ci = 0; ci < 32; ci++) {
        if (ci < 31) {
            const u64* ws = g_w2p + (ci + 1) * 800;
            for (int j = tid; j < 800; j += 256) swt[(ci + 1) & 1][j] = ws[j];
        }
        const u64* wp = swt[ci & 1] + pc * 25;
        const float* rb = ib + ci * 144;
        u64 pw0, pw1, pw2, pw3, pw4;
        pw0 = pw1 = pw2 = pw3 = pw4 = 0ull;
        #pragma unroll
        for (int rr = 0; rr < 6; rr++) {
            float4 f0 = *(const float4*)(rb + rr * 12);
            float4 f1 = *(const float4*)(rb + rr * 12 + 4);
            float4 f2 = *(const float4*)(rb + rr * 12 + 8);
            u64 R[12] = { rep2(f0.x), rep2(f0.y), rep2(f0.z), rep2(f0.w),
                          rep2(f1.x), rep2(f1.y), rep2(f1.z), rep2(f1.w),
                          rep2(f2.x), rep2(f2.y), rep2(f2.z), rep2(f2.w) };
            if (rr >= 1) {
                #pragma unroll
                for (int px = 0; px < 8; px++) {
                    ffma2(acc[1][px], R[px],     pw0);
                    ffma2(acc[1][px], R[px + 1], pw1);
                    ffma2(acc[1][px], R[px + 2], pw2);
                    ffma2(acc[1][px], R[px + 3], pw3);
                    ffma2(acc[1][px], R[px + 4], pw4);
                }
            }
            if (rr < 5) {
                const u64* wr = wp + rr * 5;
                u64 c0 = wr[0], c1 = wr[1], c2 = wr[2], c3 = wr[3], c4 = wr[4];
                #pragma unroll
                for (int px = 0; px < 8; px++) {
                    ffma2(acc[0][px], R[px],     c0);
                    ffma2(acc[0][px], R[px + 1], c1);
                    ffma2(acc[0][px], R[px + 2], c2);
                    ffma2(acc[0][px], R[px + 3], c3);
                    ffma2(acc[0][px], R[px + 4], c4);
                }
                pw0 = c0; pw1 = c1; pw2 = c2; pw3 = c3; pw4 = c4;
            }
        }
        __syncthreads();
    }

    int n = n0 + img;
    u64 sp = 0ull, qp = 0ull;
    float r0c0[8], r0c1[8], r1c0[8], r1c1[8];
    #pragma unroll
    for (int px = 0; px < 8; px++) {
        sp = add2(sp, acc[0][px]); ffma2(qp, acc[0][px], acc[0][px]);
        sp = add2(sp, acc[1][px]); ffma2(qp, acc[1][px], acc[1][px]);
        unpack2(acc[0][px], r0c0[px], r0c1[px]);
        unpack2(acc[1][px], r1c0[px], r1c1[px]);
    }
    float pm0[4], pn0[4], pm1[4], pn1[4];
    #pragma unroll
    for (int j = 0; j < 4; j++) {
        pm0[j] = fmaxf(fmaxf(r0c0[2 * j], r0c0[2 * j + 1]), fmaxf(r1c0[2 * j], r1c0[2 * j + 1]));
        pn0[j] = fminf(fminf(r0c0[2 * j], r0c0[2 * j + 1]), fminf(r1c0[2 * j], r1c0[2 * j + 1]));
        pm1[j] = fmaxf(fmaxf(r0c1[2 * j], r0c1[2 * j + 1]), fmaxf(r1c1[2 * j], r1c1[2 * j + 1]));
        pn1[j] = fminf(fminf(r0c1[2 * j], r0c1[2 * j + 1]), fminf(r1c1[2 * j], r1c1[2 * j + 1]));
    }
    int ob = n * 1024 + (2 * pc) * 16 + q * 4;
    *(float4*)(g_m2max + ob)      = make_float4(pm0[0], pm0[1], pm0[2], pm0[3]);
    *(float4*)(g_m2min + ob)      = make_float4(pn0[0], pn0[1], pn0[2], pn0[3]);
    *(float4*)(g_m2max + ob + 16) = make_float4(pm1[0], pm1[1], pm1[2], pm1[3]);
    *(float4*)(g_m2min + ob + 16) = make_float4(pn1[0], pn1[1], pn1[2], pn1[3]);

    #pragma unroll
    for (int off = 1; off < 4; off <<= 1) {
        sp = add2(sp, __shfl_xor_sync(0xffffffffu, sp, off));
        qp = add2(qp, __shfl_xor_sync(0xffffffffu, qp, off));
    }
    if (q == 0) {
        float s0, s1, q0, q1;
        unpack2(sp, s0, s1);
        unpack2(qp, q0, q1);
        atomicAdd(&g_sum2[2 * pc],     (double)s0);
        atomicAdd(&g_sum2[2 * pc + 1], (double)s1);
        atomicAdd(&g_sqs2[2 * pc],     (double)q0);
        atomicAdd(&g_sqs2[2 * pc + 1], (double)q1);
    }
}

// ---------------------------------------------------------------------------
// Launch 6: bnpool2 — fin2 inline, bnsel on pooled extrema -> h2.
// ---------------------------------------------------------------------------
__global__ __launch_bounds__(256) void k_bnpool2(const float* __restrict__ g, const float* __restrict__ be) {
    __shared__ float sA[64], sB[64];
    if (threadIdx.x < 64) {
        int c = threadIdx.x;
        const double invM = 1.0 / (4096.0 * 64.0);
        double mean = g_sum2[c] * invM;
        double var  = g_sqs2[c] * invM - mean * mean;
        float A = g[c] * rsqrtf((float)var + 1e-5f);
        sA[c] = A;
        sB[c] = be[c] - (float)mean * A;
    }
    __syncthreads();
    int tB = blockIdx.x * 256 + threadIdx.x;
    int base = tB * 4;
    int c = (base & 1023) >> 4;
    float4 mx = *(const float4*)(g_m2max + base);
    float4 mn = *(const float4*)(g_m2min + base);
    float A = sA[c], B = sB[c];
    float4 o;
    o.x = bnsel(A, B, mx.x, mn.x);
    o.y = bnsel(A, B, mx.y, mn.y);
    o.z = bnsel(A, B, mx.z, mn.z);
    o.w = bnsel(A, B, mx.w, mn.w);
    *(float4*)(g_h2 + base) = o;
}

// ---------------------------------------------------------------------------
// Launch 7: fc1 GEMM — R17: 32x64 tile, grid (8,128)=1024 CTAs, 128 thr,
// 2x8 per-thread tile, pipelined global loads, reads h2. + column stats.
// ---------------------------------------------------------------------------
__global__ __launch_bounds__(128, 8) void k_fc1() {
    __shared__ float As[16][32];               // [k][m] 2 KB
    __shared__ float Bs[16][64];               // [k][n] 4 KB
    __shared__ float scol[64], scol2[64];
    int tid = threadIdx.x;
    if (tid < 64) { scol[tid] = 0.f; scol2[tid] = 0.f; }
    __syncthreads();

    int m0 = blockIdx.y * 32;
    int n0 = blockIdx.x * 64;

    // A staging: 32 rows x 16 k = 128 float4 slots, 1 per thread
    int rA = tid >> 2, kA = (tid & 3) * 4;
    const float* Al = g_h2 + (m0 + rA) * 1024 + kA;
    // B staging: 64 rows x 16 k = 256 float4 slots, 2 per thread
    int s0 = tid * 2, s1 = s0 + 1;
    int rB0 = s0 >> 2, kB0 = (s0 & 3) * 4;
    int rB1 = s1 >> 2, kB1 = (s1 & 3) * 4;
    const float* Bl0 = g_wf1q + (n0 + rB0) * 1024 + kB0;
    const float* Bl1 = g_wf1q + (n0 + rB1) * 1024 + kB1;

    int rowi = (tid >> 3) * 2;                 // 16 groups x 2 rows = 32
    int colg = (tid & 7) * 8;                  // 8 groups x 8 cols = 64

    u64 accp[2][4];
    #pragma unroll
    for (int i = 0; i < 2; i++)
        #pragma unroll
        for (int j = 0; j < 4; j++) accp[i][j] = 0ull;

    float4 aw = *(const float4*)Al;
    float4 bw0 = *(const float4*)Bl0, bw1 = *(const float4*)Bl1;

    for (int k0 = 0; k0 < 1024; k0 += 16) {
        float4 av = aw, b0v = bw0, b1v = bw1;
        __syncthreads();
        As[kA + 0][rA] = av.x; As[kA + 1][rA] = av.y;
        As[kA + 2][rA] = av.z; As[kA + 3][rA] = av.w;
        Bs[kB0 + 0][rB0] = b0v.x; Bs[kB0 + 1][rB0] = b0v.y;
        Bs[kB0 + 2][rB0] = b0v.z; Bs[kB0 + 3][rB0] = b0v.w;
        Bs[kB1 + 0][rB1] = b1v.x; Bs[kB1 + 1][rB1] = b1v.y;
        Bs[kB1 + 2][rB1] = b1v.z; Bs[kB1 + 3][rB1] = b1v.w;
        __syncthreads();
        if (k0 < 1008) {
            aw  = *(const float4*)(Al + k0 + 16);
            bw0 = *(const float4*)(Bl0 + k0 + 16);
            bw1 = *(const float4*)(Bl1 + k0 + 16);
        }
        #pragma unroll
        for (int k = 0; k < 16; k++) {
            float2 a = *(const float2*)&As[k][rowi];
            ulonglong2 b01 = *(const ulonglong2*)&Bs[k][colg];
            ulonglong2 b23 = *(const ulonglong2*)&Bs[k][colg + 4];
            u64 a0 = rep2(a.x), a1 = rep2(a.y);
            ffma2(accp[0][0], a0, b01.x); ffma2(accp[0][1], a0, b01.y);
            ffma2(accp[0][2], a0, b23.x); ffma2(accp[0][3], a0, b23.y);
            ffma2(accp[1][0], a1, b01.x); ffma2(accp[1][1], a1, b01.y);
            ffma2(accp[1][2], a1, b23.x); ffma2(accp[1][3], a1, b23.y);
        }
    }

    float acc[2][8];
    #pragma unroll
    for (int i = 0; i < 2; i++) {
        unpack2(accp[i][0], acc[i][0], acc[i][1]);
        unpack2(accp[i][1], acc[i][2], acc[i][3]);
        unpack2(accp[i][2], acc[i][4], acc[i][5]);
        unpack2(accp[i][3], acc[i][6], acc[i][7]);
    }
    #pragma unroll
    for (int i = 0; i < 2; i++) {
        int row = m0 + rowi + i;
        float* yp = g_y3 + row * 512 + n0 + colg;
        *(float4*)yp       = make_float4(acc[i][0], acc[i][1], acc[i][2], acc[i][3]);
        *(float4*)(yp + 4) = make_float4(acc[i][4], acc[i][5], acc[i][6], acc[i][7]);
    }
    #pragma unroll
    for (int j = 0; j < 8; j++) {
        float s = acc[0][j] + acc[1][j];
        float q = fmaf(acc[0][j], acc[0][j], acc[1][j] * acc[1][j]);
        atomicAdd(&scol[colg + j], s);
        atomicAdd(&scol2[colg + j], q);
    }
    __syncthreads();
    if (tid < 64) {
        atomicAdd(&g_sum3[n0 + tid], (double)scol[tid]);
        atomicAdd(&g_sqs3[n0 + tid], (double)scol2[tid]);
    }
}

// ---------------------------------------------------------------------------
// Launch 8: fc2 fused with bn1d+relu. Warp per row.
// ---------------------------------------------------------------------------
__global__ __launch_bounds__(256) void k_fc2(float* __restrict__ out, const float* __restrict__ bf2,
                                             const float* __restrict__ g3, const float* __restrict__ be3) {
    __shared__ float sw[5120];
    __shared__ float sA[512], sB[512];
    __shared__ float sb[16];
    for (int i = threadIdx.x; i < 5120; i += 256) sw[i] = g_wf2q[i];
    for (int i = threadIdx.x; i < 512; i += 256) {
        const double invM = 1.0 / 4096.0;
        double mean = g_sum3[i] * invM;
        double var  = g_sqs3[i] * invM - mean * mean;
        float A = g3[i] * rsqrtf((float)var + 1e-5f);
        sA[i] = A;
        sB[i] = be3[i] - (float)mean * A;
    }
    if (threadIdx.x < 10) sb[threadIdx.x] = bf2[threadIdx.x];
    __syncthreads();

    int warp = threadIdx.x >> 5, lane = threadIdx.x & 31;
    int n = blockIdx.x * 8 + warp;
    const float* yr = g_y3 + n * 512;
    float acc[10];
    #pragma unroll
    for (int o = 0; o < 10; o++) acc[o] = 0.f;
    for (int f = lane; f < 512; f += 32) {
        float a = fmaxf(fmaf(sA[f], yr[f], sB[f]), 0.f);
        #pragma unroll
        for (int o = 0; o < 10; o++) acc[o] = fmaf(a, sw[o * 512 + f], acc[o]);
    }
    #pragma unroll
    for (int o = 0; o < 10; o++) {
        float s = acc[o];
        #pragma unroll
        for (int off = 16; off; off >>= 1) s += __shfl_xor_sync(0xffffffffu, s, off);
        if (lane == 0) out[n * 10 + o] = s + sb[o];
    }
}

// ---------------------------------------------------------------------------
extern "C" void kernel_launch(void* const* d_in, const int* in_sizes, int n_in,
                              void* d_out, int out_size) {
    const float* x   = (const float*)d_in[0];
    const float* w1  = (const float*)d_in[1];
    const float* g1  = (const float*)d_in[3];
    const float* be1 = (const float*)d_in[4];
    const float* w2  = (const float*)d_in[5];
    const float* g2  = (const float*)d_in[7];
    const float* be2 = (const float*)d_in[8];
    const float* wf1 = (const float*)d_in[9];
    const float* g3  = (const float*)d_in[11];
    const float* be3 = (const float*)d_in[12];
    const float* wf2 = (const float*)d_in[13];
    const float* bf2 = (const float*)d_in[14];
    float* out = (float*)d_out;

    k_absmax<<<96, 256>>>(w1, w2, wf1, wf2);        // 1
    k_quantA<<<104, 256>>>(w1, w2);                 // 2
    k_quantB<<<288, 256>>>(wf1, wf2);               // 3
    k_conv1<<<4096, 192>>>(x);                      // 4  <- profiled
    k_conv2<<<2048, 256>>>(g1, be1);                // 5
    k_bnpool2<<<4096, 256>>>(g2, be2);              // 6
    dim3 g_fc1(8, 128);
    k_fc1<<<g_fc1, 128>>>();                        // 7
    k_fc2<<<512, 256>>>(out, bf2, g3, be3);         // 8
}